// round 15
// baseline (speedup 1.0000x reference)
#include <cuda_runtime.h>
#include <cuda_bf16.h>
#include <math.h>
#include <stdint.h>

#define B4 4
#define C512 512
#define HW 4096
#define NG 32
typedef __nv_bfloat16 bf16;

// ---------------------------------------------------------------------------
// Scratch (device globals — no runtime allocation allowed)
// g_qkv: [b][1536][s]  rows 0..511=q, 512..1023=k, 1024..1535=v  (bf16)
// g_oT : [b][s][c]  attention output, s-major (feeds proj as TB=1 operand)
// ---------------------------------------------------------------------------
__device__ bf16 g_h  [(size_t)B4 * C512 * HW];
__device__ bf16 g_qkv[(size_t)B4 * 3 * C512 * HW];
__device__ bf16 g_oT [(size_t)B4 * HW * C512];
__device__ bf16 g_p  [(size_t)B4 * HW * HW];            // e = exp(scores) bf16
__device__ bf16 g_w  [4 * C512 * C512];
__device__ float g_bqkv[3 * C512];
__device__ float g_ps[(size_t)B4 * HW * 32];            // per-(row, jtile) partials
__device__ float g_ri[(size_t)B4 * HW];                 // 1/rowsum

// ---------------------------------------------------------------------------
// Helpers
// ---------------------------------------------------------------------------
__device__ __forceinline__ uint32_t packbf(float e0, float e1) {
    uint32_t r;
    asm("cvt.rn.bf16x2.f32 %0, %1, %2;" : "=r"(r) : "f"(e1), "f"(e0));
    return r;
}
__device__ __forceinline__ uint32_t cvta_s(const void* p) {
    return (uint32_t)__cvta_generic_to_shared(p);
}
__device__ __forceinline__ void ldsm4(uint32_t* r, uint32_t a) {
    asm volatile("ldmatrix.sync.aligned.m8n8.x4.shared.b16 {%0,%1,%2,%3}, [%4];"
                 : "=r"(r[0]), "=r"(r[1]), "=r"(r[2]), "=r"(r[3]) : "r"(a));
}
__device__ __forceinline__ void ldsm4t(uint32_t* r, uint32_t a) {
    asm volatile("ldmatrix.sync.aligned.m8n8.x4.trans.shared.b16 {%0,%1,%2,%3}, [%4];"
                 : "=r"(r[0]), "=r"(r[1]), "=r"(r[2]), "=r"(r[3]) : "r"(a));
}
__device__ __forceinline__ void cpasync16(uint32_t dst, const void* src) {
    asm volatile("cp.async.cg.shared.global [%0], [%1], 16;" :: "r"(dst), "l"(src));
}
__device__ __forceinline__ void mma_bf16(float* c, const uint32_t* a, const uint32_t* b) {
    asm volatile(
        "mma.sync.aligned.m16n8k16.row.col.f32.bf16.bf16.f32 "
        "{%0,%1,%2,%3}, {%4,%5,%6,%7}, {%8,%9}, {%0,%1,%2,%3};"
        : "+f"(c[0]), "+f"(c[1]), "+f"(c[2]), "+f"(c[3])
        : "r"(a[0]), "r"(a[1]), "r"(a[2]), "r"(a[3]), "r"(b[0]), "r"(b[1]));
}

// ---------------------------------------------------------------------------
// Weight fp32 -> bf16 ; bias concat
// ---------------------------------------------------------------------------
__global__ __launch_bounds__(256) void convw_kernel(
    const float* __restrict__ w0, const float* __restrict__ w1,
    const float* __restrict__ w2, const float* __restrict__ w3,
    bf16* __restrict__ out)
{
    int i = blockIdx.x * 256 + threadIdx.x;
    const float* src = (i < 262144) ? w0 : (i < 524288) ? w1
                      : (i < 786432) ? w2 : w3;
    out[i] = __float2bfloat16(src[i & 262143]);
}
__global__ __launch_bounds__(256) void convb_kernel(
    const float* __restrict__ b0, const float* __restrict__ b1,
    const float* __restrict__ b2, float* __restrict__ out)
{
    int i = blockIdx.x * 256 + threadIdx.x;
    out[i] = (i < 512) ? b0[i] : (i < 1024) ? b1[i - 512] : b2[i - 1024];
}

// ---------------------------------------------------------------------------
// GroupNorm -> bf16 [b][c][s]
// ---------------------------------------------------------------------------
__global__ __launch_bounds__(256) void groupnorm_kernel(
    const float* __restrict__ x, const float* __restrict__ gamma,
    const float* __restrict__ beta, bf16* __restrict__ out)
{
    const int GSZ = (C512 / NG) * HW;
    int b = blockIdx.x >> 5;
    int g = blockIdx.x & 31;
    const float* xp = x + ((size_t)b * C512 + g * (C512 / NG)) * HW;
    bf16* op = out + ((size_t)b * C512 + g * (C512 / NG)) * HW;

    float s = 0.f, sq = 0.f;
    for (int i = threadIdx.x * 4; i < GSZ; i += blockDim.x * 4) {
        float4 v = *(const float4*)(xp + i);
        s  += v.x + v.y + v.z + v.w;
        sq += v.x * v.x + v.y * v.y + v.z * v.z + v.w * v.w;
    }
    __shared__ float red0[8], red1[8];
    #pragma unroll
    for (int o = 16; o > 0; o >>= 1) {
        s  += __shfl_xor_sync(0xffffffffu, s, o);
        sq += __shfl_xor_sync(0xffffffffu, sq, o);
    }
    if ((threadIdx.x & 31) == 0) { red0[threadIdx.x >> 5] = s; red1[threadIdx.x >> 5] = sq; }
    __syncthreads();
    s = 0.f; sq = 0.f;
    #pragma unroll
    for (int i = 0; i < 8; i++) { s += red0[i]; sq += red1[i]; }
    float mean = s / GSZ;
    float var  = sq / GSZ - mean * mean;
    float rstd = rsqrtf(var + 1e-6f);

    for (int i = threadIdx.x * 4; i < GSZ; i += blockDim.x * 4) {
        int c = g * (C512 / NG) + (i >> 12);
        float w  = gamma[c] * rstd;
        float bb = beta[c] - mean * w;
        float4 v = *(const float4*)(xp + i);
        uint2 pk;
        pk.x = packbf(v.x * w + bb, v.y * w + bb);
        pk.y = packbf(v.z * w + bb, v.w * w + bb);
        *(uint2*)(op + i) = pk;
    }
}

// ---------------------------------------------------------------------------
// bf16 HMMA GEMM: 256 threads, 8 warps (4m x 2n), block 256x128, warp 64x64,
// BK=64, 3-stage cp.async (issue at kt+2), register fragment double-buffer.
// C[m][n] = alpha * sum_k A(m,k)*B(k,n)
// TA=0: A row-major MxK. TA=1: A stored KxM [ldmatrix.trans]
// TB=1: B stored NxK.    TB=0: B row-major KxN [trans]
// smem stage: A 32KB ([256r][64k], chunk swz c^(r&7)) or ([64k][256m] rows of
//   32 chunks, swz c^(k&7)); B 16KB (as R14). 3x48KB = 144KB, 1 CTA/SM.
// EPI: 0 normal (bias[m], optional fp32 resid)
//      1 p=bf16(exp(alpha*acc)) + per-(row,jtile) partial sums
//      2 multiply by nsc[m-row] (deferred softmax norm), bf16 out
// ---------------------------------------------------------------------------
#define STG_A 32768
#define STG_B 16384
#define SMEM_GEMM (3 * (STG_A + STG_B))

template <int TA, int TB, int OUTBF, int EPI>
__global__ __launch_bounds__(256, 1) void bfgemm(
    int M, int N, int K,
    const bf16* __restrict__ A, long long sA,
    const bf16* __restrict__ B, long long sB,
    void* __restrict__ Cv, long long sC,
    const float* __restrict__ bias,
    const float* __restrict__ resid, long long sR,
    float* __restrict__ psum,
    const float* __restrict__ nsc,
    float alpha)
{
    extern __shared__ bf16 smbuf[];
    const int tid = threadIdx.x, lane = tid & 31, wid = tid >> 5;
    const int bm0 = blockIdx.y * 256, bn0 = blockIdx.x * 128;
    const int bz = blockIdx.z;
    A += (size_t)bz * sA;
    B += (size_t)bz * sB;

    const int lda = TA ? M : K;
    const int ldb = TB ? K : N;
    const long long stepA = TA ? (long long)64 * lda : 64;   // per k-tile
    const long long stepB = TB ? 64 : (long long)64 * ldb;

    const uint32_t As_u = cvta_s(smbuf);
    const uint32_t Bs_u = As_u + 3 * STG_A;

    // cp.async staging: A 2048 chunks (8/thread), B 1024 chunks (4/thread)
    uint32_t aOfs[8], aDst[8], bOfs[4], bDst[4];
    #pragma unroll
    for (int i = 0; i < 8; i++) {
        const int g = tid + i * 256;
        if (TA == 0) {              // [256r][64k] rows of 8 chunks
            int r = g >> 3, c = g & 7;
            aOfs[i] = (uint32_t)(r * lda + c * 8);
            aDst[i] = (uint32_t)(r * 8 + (c ^ (r & 7))) * 16;
        } else {                    // [64k][256m] rows of 32 chunks
            int k = g >> 5, c = g & 31;
            aOfs[i] = (uint32_t)(k * lda + c * 8);
            aDst[i] = (uint32_t)(k * 32 + (c ^ (k & 7))) * 16;
        }
    }
    #pragma unroll
    for (int i = 0; i < 4; i++) {
        const int g = tid + i * 256;
        if (TB == 1) {              // [128r][64k] rows of 8 chunks
            int r = g >> 3, c = g & 7;
            bOfs[i] = (uint32_t)(r * ldb + c * 8);
            bDst[i] = (uint32_t)(r * 8 + (c ^ (r & 7))) * 16;
        } else {                    // [64k][128n] rows of 16 chunks
            int k = g >> 4, c = g & 15;
            bOfs[i] = (uint32_t)(k * ldb + c * 8);
            bDst[i] = (uint32_t)(k * 16 + (c ^ (k & 7))) * 16;
        }
    }
    const bf16* Abase = A + (TA == 0 ? (size_t)bm0 * lda : (size_t)bm0);
    const bf16* Bbase = B + (TB == 1 ? (size_t)bn0 * ldb : (size_t)bn0);

    // ldmatrix fragment byte offsets per ks (0..3)
    const int quad = lane >> 3, lrow = lane & 7;
    const int wm0 = (wid & 3) * 64, wn0 = (wid >> 2) * 64;
    uint32_t fA[4][4], fB[4][4];
    #pragma unroll
    for (int ks = 0; ks < 4; ks++) {
        #pragma unroll
        for (int mi = 0; mi < 4; mi++) {
            if (TA == 0) {
                int r = wm0 + mi * 16 + (quad & 1) * 8 + lrow;
                int c = 2 * ks + (quad >> 1);
                fA[ks][mi] = (uint32_t)(r * 8 + (c ^ (r & 7))) * 16;
            } else {
                int k = ks * 16 + (quad >> 1) * 8 + lrow;
                int c = ((wm0 + mi * 16) >> 3) + (quad & 1);
                fA[ks][mi] = (uint32_t)(k * 32 + (c ^ (k & 7))) * 16;
            }
        }
        #pragma unroll
        for (int nj = 0; nj < 4; nj++) {
            if (TB == 1) {
                int r = wn0 + nj * 16 + (quad & 1) * 8 + lrow;
                int c = 2 * ks + (quad >> 1);
                fB[ks][nj] = (uint32_t)(r * 8 + (c ^ (r & 7))) * 16;
            } else {
                int k = ks * 16 + (quad >> 1) * 8 + lrow;
                int c = ((wn0 + nj * 16) >> 3) + (quad & 1);
                fB[ks][nj] = (uint32_t)(k * 16 + (c ^ (k & 7))) * 16;
            }
        }
    }

    auto issue = [&](int st, int kt) {
        const bf16* ag = Abase + (size_t)kt * stepA;
        const bf16* bg = Bbase + (size_t)kt * stepB;
        const uint32_t ad = As_u + st * STG_A;
        const uint32_t bd = Bs_u + st * STG_B;
        #pragma unroll
        for (int i = 0; i < 8; i++) cpasync16(ad + aDst[i], ag + aOfs[i]);
        #pragma unroll
        for (int i = 0; i < 4; i++) cpasync16(bd + bDst[i], bg + bOfs[i]);
    };

    uint32_t aFr[2][4][4], bFr[2][4][4];
    auto loadfrag = [&](int set, int st, int ks) {
        const uint32_t ab = As_u + st * STG_A;
        const uint32_t bb = Bs_u + st * STG_B;
        #pragma unroll
        for (int mi = 0; mi < 4; mi++) {
            if (TA == 0) ldsm4(aFr[set][mi], ab + fA[ks][mi]);
            else         ldsm4t(aFr[set][mi], ab + fA[ks][mi]);
        }
        #pragma unroll
        for (int nj = 0; nj < 4; nj++) {
            if (TB == 1) ldsm4(bFr[set][nj], bb + fB[ks][nj]);
            else         ldsm4t(bFr[set][nj], bb + fB[ks][nj]);
        }
    };

    float acc[4][8][4] = {};
    auto domma = [&](int set) {
        #pragma unroll
        for (int mi = 0; mi < 4; mi++)
            #pragma unroll
            for (int nj = 0; nj < 4; nj++) {
                uint32_t bl[2] = {bFr[set][nj][0], bFr[set][nj][2]};
                uint32_t bh[2] = {bFr[set][nj][1], bFr[set][nj][3]};
                mma_bf16(acc[mi][nj * 2 + 0], aFr[set][mi], bl);
                mma_bf16(acc[mi][nj * 2 + 1], aFr[set][mi], bh);
            }
    };

    const int nk = K / 64;
    issue(0, 0); asm volatile("cp.async.commit_group;" ::: "memory");
    issue(1, 1); asm volatile("cp.async.commit_group;" ::: "memory");
    asm volatile("cp.async.wait_group 1;" ::: "memory");
    __syncthreads();
    loadfrag(0, 0, 0);

    for (int kt = 0; kt < nk; kt++) {
        const int st = kt % 3;
        loadfrag(1, st, 1);
        if (kt + 2 < nk) issue((kt + 2) % 3, kt + 2);
        asm volatile("cp.async.commit_group;" ::: "memory");
        domma(0);
        loadfrag(0, st, 2);
        domma(1);
        loadfrag(1, st, 3);
        domma(0);
        asm volatile("cp.async.wait_group 1;" ::: "memory");
        __syncthreads();
        if (kt + 1 < nk) loadfrag(0, (kt + 1) % 3, 0);
        domma(1);
    }

    // ---------------- epilogue ----------------
    const int lr = lane >> 2, lc = lane & 3;

    if (EPI == 1) {
        __syncthreads();
        float* ps = (float*)smbuf;             // [256][2]
        bf16* C = (bf16*)Cv + (size_t)bz * sC;
        #pragma unroll
        for (int mi = 0; mi < 4; mi++) {
            const int r0 = bm0 + wm0 + mi * 16 + lr;
            const int col = bn0 + wn0 + 2 * lc;
            uint32_t* C0 = (uint32_t*)(C + (size_t)r0 * N + col);
            uint32_t* C1 = (uint32_t*)(C + (size_t)(r0 + 8) * N + col);
            float s0 = 0.f, s1 = 0.f;
            #pragma unroll
            for (int j = 0; j < 8; j++) {
                float e00 = __expf(acc[mi][j][0] * alpha);
                float e01 = __expf(acc[mi][j][1] * alpha);
                float e10 = __expf(acc[mi][j][2] * alpha);
                float e11 = __expf(acc[mi][j][3] * alpha);
                C0[j * 4] = packbf(e00, e01);
                C1[j * 4] = packbf(e10, e11);
                s0 += e00 + e01;
                s1 += e10 + e11;
            }
            float v0 = s0, v1 = s1;
            v0 += __shfl_xor_sync(0xffffffffu, v0, 1);
            v0 += __shfl_xor_sync(0xffffffffu, v0, 2);
            v1 += __shfl_xor_sync(0xffffffffu, v1, 1);
            v1 += __shfl_xor_sync(0xffffffffu, v1, 2);
            if (lc == 0) {
                ps[(wm0 + mi * 16 + lr) * 2 + (wn0 >> 6)] = v0;
                ps[(wm0 + mi * 16 + 8 + lr) * 2 + (wn0 >> 6)] = v1;
            }
        }
        __syncthreads();
        float t = ps[tid * 2 + 0] + ps[tid * 2 + 1];
        psum[((size_t)bz * HW + bm0 + tid) * 32 + blockIdx.x] = t;
        return;
    }

    #pragma unroll
    for (int mi = 0; mi < 4; mi++) {
        const int r0 = bm0 + wm0 + mi * 16 + lr;
        const int col = bn0 + wn0 + 2 * lc;
        if (OUTBF) {
            bf16* C = (bf16*)Cv + (size_t)bz * sC;
            uint32_t* C0 = (uint32_t*)(C + (size_t)r0 * N + col);
            uint32_t* C1 = (uint32_t*)(C + (size_t)(r0 + 8) * N + col);
            float bv0 = 0.f, bv1 = 0.f;          // EPI==0 bias[m]
            if (EPI == 0 && bias) { bv0 = bias[r0]; bv1 = bias[r0 + 8]; }
            float f0 = 1.f, f1 = 1.f;            // EPI==2 row scale
            if (EPI == 2) {
                f0 = nsc[(size_t)bz * HW + r0];
                f1 = nsc[(size_t)bz * HW + r0 + 8];
            }
            #pragma unroll
            for (int j = 0; j < 8; j++) {
                C0[j * 4] = packbf(acc[mi][j][0] * alpha * f0 + bv0,
                                   acc[mi][j][1] * alpha * f0 + bv0);
                C1[j * 4] = packbf(acc[mi][j][2] * alpha * f1 + bv1,
                                   acc[mi][j][3] * alpha * f1 + bv1);
            }
        } else {
            float* C = (float*)Cv + (size_t)bz * sC;
            float* C0 = C + (size_t)r0 * N + col;
            float* C1 = C + (size_t)(r0 + 8) * N + col;
            const float bv0 = bias ? bias[r0] : 0.f;
            const float bv1 = bias ? bias[r0 + 8] : 0.f;
            const float* R0 = resid ? resid + (size_t)bz * sR + (size_t)r0 * N + col : (const float*)0;
            const float* R1 = resid ? resid + (size_t)bz * sR + (size_t)(r0 + 8) * N + col : (const float*)0;
            #pragma unroll
            for (int j = 0; j < 8; j++) {
                float2 v0 = make_float2(acc[mi][j][0] * alpha + bv0,
                                        acc[mi][j][1] * alpha + bv0);
                float2 v1 = make_float2(acc[mi][j][2] * alpha + bv1,
                                        acc[mi][j][3] * alpha + bv1);
                if (resid) {
                    float2 q0 = *(const float2*)(R0 + j * 8);
                    float2 q1 = *(const float2*)(R1 + j * 8);
                    v0.x += q0.x; v0.y += q0.y;
                    v1.x += q1.x; v1.y += q1.y;
                }
                *(float2*)(C0 + j * 8) = v0;
                *(float2*)(C1 + j * 8) = v1;
            }
        }
    }
}

// ---------------------------------------------------------------------------
// rowinv: 1 / sum of 32 partials per row
// ---------------------------------------------------------------------------
__global__ __launch_bounds__(256) void rowinv_kernel(
    const float* __restrict__ psum, float* __restrict__ rinv)
{
    const int idx = blockIdx.x * 256 + threadIdx.x;
    const float4* p = (const float4*)(psum + (size_t)idx * 32);
    float s = 0.f;
    #pragma unroll
    for (int i = 0; i < 8; i++) {
        float4 v = p[i];
        s += v.x + v.y + v.z + v.w;
    }
    rinv[idx] = 1.f / s;
}

// ---------------------------------------------------------------------------
// Launcher
// ---------------------------------------------------------------------------
extern "C" void kernel_launch(void* const* d_in, const int* in_sizes, int n_in,
                              void* d_out, int out_size)
{
    (void)in_sizes; (void)n_in; (void)out_size;
    const float* x    = (const float*)d_in[0];
    const float* gn_w = (const float*)d_in[1];
    const float* gn_b = (const float*)d_in[2];
    const float* wq   = (const float*)d_in[3];
    const float* bq   = (const float*)d_in[4];
    const float* wk   = (const float*)d_in[5];
    const float* bk   = (const float*)d_in[6];
    const float* wv   = (const float*)d_in[7];
    const float* bv   = (const float*)d_in[8];
    const float* wo   = (const float*)d_in[9];
    const float* bo   = (const float*)d_in[10];
    float* out = (float*)d_out;

    bf16 *h_, *qkv, *oT, *p, *w;
    float *bqkv, *ps, *ri;
    cudaGetSymbolAddress((void**)&h_,  g_h);
    cudaGetSymbolAddress((void**)&qkv, g_qkv);
    cudaGetSymbolAddress((void**)&oT,  g_oT);
    cudaGetSymbolAddress((void**)&p,   g_p);
    cudaGetSymbolAddress((void**)&w,   g_w);
    cudaGetSymbolAddress((void**)&bqkv, g_bqkv);
    cudaGetSymbolAddress((void**)&ps,  g_ps);
    cudaGetSymbolAddress((void**)&ri,  g_ri);

    cudaFuncSetAttribute(bfgemm<0, 0, 1, 0>, cudaFuncAttributeMaxDynamicSharedMemorySize, SMEM_GEMM);
    cudaFuncSetAttribute(bfgemm<1, 0, 1, 1>, cudaFuncAttributeMaxDynamicSharedMemorySize, SMEM_GEMM);
    cudaFuncSetAttribute(bfgemm<0, 1, 1, 2>, cudaFuncAttributeMaxDynamicSharedMemorySize, SMEM_GEMM);
    cudaFuncSetAttribute(bfgemm<0, 1, 0, 0>, cudaFuncAttributeMaxDynamicSharedMemorySize, SMEM_GEMM);

    const long long SC  = (long long)C512 * HW;
    const long long SC3 = 3 * SC;
    const long long SS  = (long long)HW * HW;
    const int WSZ = C512 * C512;
    const float scale = 0.044194173824159216f;    // 512^-0.5

    convw_kernel<<<4096, 256>>>(wq, wk, wv, wo, w);
    convb_kernel<<<6, 256>>>(bq, bk, bv, bqkv);
    groupnorm_kernel<<<B4 * NG, 256>>>(x, gn_w, gn_b, h_);

    // Fused QKV: qkv[m][s] = sum_c Wqkv[m][c] * h[c][s] + bqkv[m]
    // A=Wqkv row-major (TA=0), B=h KxN (TB=0). M=1536 -> 6 m-tiles.
    dim3 gQKV(HW / 128, 1536 / 256, B4);          // (32, 6, 4)
    bfgemm<0, 0, 1, 0><<<gQKV, 256, SMEM_GEMM>>>(1536, HW, C512,
        w, 0, h_, SC, qkv, SC3, bqkv, nullptr, 0, nullptr, nullptr, 1.f);

    // p[i][j] = exp(scale * sum_c q[c][i] k[c][j]); partial row sums
    // A=q KxM (TA=1), B=k KxN (TB=0). M=N=4096.
    dim3 gS(HW / 128, HW / 256, B4);              // (32, 16, 4)
    bfgemm<1, 0, 1, 1><<<gS, 256, SMEM_GEMM>>>(HW, HW, C512,
        qkv, SC3, qkv + SC, SC3, p, SS, nullptr, nullptr, 0, ps, nullptr, scale);

    rowinv_kernel<<<B4 * HW / 256, 256>>>(ps, ri);

    // oT[i][c] = (sum_j p[i][j] * v[c][j]) * rinv[i]
    // A=p row-major MxK (TA=0, M=4096, K=4096), B=v NxK (TB=1, N=512, ldb=HW).
    dim3 gO(C512 / 128, HW / 256, B4);            // (4, 16, 4)
    bfgemm<0, 1, 1, 2><<<gO, 256, SMEM_GEMM>>>(HW, C512, HW,
        p, SS, qkv + 2 * SC, SC3, oT, SC, nullptr, nullptr, 0, nullptr, ri, 1.f);

    // out[m][s] = sum_c Wo[m][c] * oT[s][c] + bo[m] + x[m][s]
    // A=Wo row-major (TA=0), B=oT NxK (TB=1, N=4096, ldb=512). M=512.
    dim3 gP(HW / 128, C512 / 256, B4);            // (32, 2, 4)
    bfgemm<0, 1, 0, 0><<<gP, 256, SMEM_GEMM>>>(C512, HW, C512,
        w + 3 * WSZ, 0, oT, SC, out, SC, bo, x, SC, nullptr, nullptr, 1.f);
}

// round 16
// speedup vs baseline: 1.1140x; 1.1140x over previous
#include <cuda_runtime.h>
#include <cuda_bf16.h>
#include <math.h>
#include <stdint.h>

#define B4 4
#define C512 512
#define HW 4096
#define NG 32
typedef __nv_bfloat16 bf16;

// ---------------------------------------------------------------------------
// Scratch (device globals — no runtime allocation allowed)
// g_qkv: [b][1536][s]  rows 0..511=q, 512..1023=k, 1024..1535=v  (bf16)
// ---------------------------------------------------------------------------
__device__ bf16 g_h  [(size_t)B4 * C512 * HW];
__device__ bf16 g_qkv[(size_t)B4 * 3 * C512 * HW];
__device__ bf16 g_o  [(size_t)B4 * C512 * HW];
__device__ bf16 g_p  [(size_t)B4 * HW * HW];            // e = exp(scores) bf16
__device__ bf16 g_w  [4 * C512 * C512];
__device__ float g_bqkv[3 * C512];
__device__ float g_ps[(size_t)B4 * HW * 32];            // per-(row, jtile) partials
__device__ float g_ri[(size_t)B4 * HW];                 // 1/rowsum

// ---------------------------------------------------------------------------
// Helpers
// ---------------------------------------------------------------------------
__device__ __forceinline__ uint32_t packbf(float e0, float e1) {
    uint32_t r;
    asm("cvt.rn.bf16x2.f32 %0, %1, %2;" : "=r"(r) : "f"(e1), "f"(e0));
    return r;
}
__device__ __forceinline__ uint32_t cvta_s(const void* p) {
    return (uint32_t)__cvta_generic_to_shared(p);
}
__device__ __forceinline__ void ldsm4(uint32_t* r, uint32_t a) {
    asm volatile("ldmatrix.sync.aligned.m8n8.x4.shared.b16 {%0,%1,%2,%3}, [%4];"
                 : "=r"(r[0]), "=r"(r[1]), "=r"(r[2]), "=r"(r[3]) : "r"(a));
}
__device__ __forceinline__ void ldsm4t(uint32_t* r, uint32_t a) {
    asm volatile("ldmatrix.sync.aligned.m8n8.x4.trans.shared.b16 {%0,%1,%2,%3}, [%4];"
                 : "=r"(r[0]), "=r"(r[1]), "=r"(r[2]), "=r"(r[3]) : "r"(a));
}
__device__ __forceinline__ void cpasync16(uint32_t dst, const void* src) {
    asm volatile("cp.async.cg.shared.global [%0], [%1], 16;" :: "r"(dst), "l"(src));
}
__device__ __forceinline__ void mma_bf16(float* c, const uint32_t* a, const uint32_t* b) {
    asm volatile(
        "mma.sync.aligned.m16n8k16.row.col.f32.bf16.bf16.f32 "
        "{%0,%1,%2,%3}, {%4,%5,%6,%7}, {%8,%9}, {%0,%1,%2,%3};"
        : "+f"(c[0]), "+f"(c[1]), "+f"(c[2]), "+f"(c[3])
        : "r"(a[0]), "r"(a[1]), "r"(a[2]), "r"(a[3]), "r"(b[0]), "r"(b[1]));
}

// ---------------------------------------------------------------------------
// Weight fp32 -> bf16 ; bias concat
// ---------------------------------------------------------------------------
__global__ __launch_bounds__(256) void convw_kernel(
    const float* __restrict__ w0, const float* __restrict__ w1,
    const float* __restrict__ w2, const float* __restrict__ w3,
    bf16* __restrict__ out)
{
    int i = blockIdx.x * 256 + threadIdx.x;
    const float* src = (i < 262144) ? w0 : (i < 524288) ? w1
                      : (i < 786432) ? w2 : w3;
    out[i] = __float2bfloat16(src[i & 262143]);
}
__global__ __launch_bounds__(256) void convb_kernel(
    const float* __restrict__ b0, const float* __restrict__ b1,
    const float* __restrict__ b2, float* __restrict__ out)
{
    int i = blockIdx.x * 256 + threadIdx.x;
    out[i] = (i < 512) ? b0[i] : (i < 1024) ? b1[i - 512] : b2[i - 1024];
}

// ---------------------------------------------------------------------------
// GroupNorm -> bf16 [b][c][s]
// ---------------------------------------------------------------------------
__global__ __launch_bounds__(256) void groupnorm_kernel(
    const float* __restrict__ x, const float* __restrict__ gamma,
    const float* __restrict__ beta, bf16* __restrict__ out)
{
    const int GSZ = (C512 / NG) * HW;
    int b = blockIdx.x >> 5;
    int g = blockIdx.x & 31;
    const float* xp = x + ((size_t)b * C512 + g * (C512 / NG)) * HW;
    bf16* op = out + ((size_t)b * C512 + g * (C512 / NG)) * HW;

    float s = 0.f, sq = 0.f;
    for (int i = threadIdx.x * 4; i < GSZ; i += blockDim.x * 4) {
        float4 v = *(const float4*)(xp + i);
        s  += v.x + v.y + v.z + v.w;
        sq += v.x * v.x + v.y * v.y + v.z * v.z + v.w * v.w;
    }
    __shared__ float red0[8], red1[8];
    #pragma unroll
    for (int o = 16; o > 0; o >>= 1) {
        s  += __shfl_xor_sync(0xffffffffu, s, o);
        sq += __shfl_xor_sync(0xffffffffu, sq, o);
    }
    if ((threadIdx.x & 31) == 0) { red0[threadIdx.x >> 5] = s; red1[threadIdx.x >> 5] = sq; }
    __syncthreads();
    s = 0.f; sq = 0.f;
    #pragma unroll
    for (int i = 0; i < 8; i++) { s += red0[i]; sq += red1[i]; }
    float mean = s / GSZ;
    float var  = sq / GSZ - mean * mean;
    float rstd = rsqrtf(var + 1e-6f);

    for (int i = threadIdx.x * 4; i < GSZ; i += blockDim.x * 4) {
        int c = g * (C512 / NG) + (i >> 12);
        float w  = gamma[c] * rstd;
        float bb = beta[c] - mean * w;
        float4 v = *(const float4*)(xp + i);
        uint2 pk;
        pk.x = packbf(v.x * w + bb, v.y * w + bb);
        pk.y = packbf(v.z * w + bb, v.w * w + bb);
        *(uint2*)(op + i) = pk;
    }
}

// ---------------------------------------------------------------------------
// bf16 HMMA GEMM: 128 threads, 4 warps (2x2), warp tile 64x64, BK=64,
// 3-stage cp.async pipeline (issue at kt+2), register fragment double-buffer.
// Incremental global-issue pointers (pure IADD per iteration, no IMAD.WIDE).
// C[m][n] = alpha * sum_k A(m,k)*B(k,n)
// TA=0: A row-major MxK. TA=1: A stored KxM [ldmatrix.trans]
// TB=1: B stored NxK.    TB=0: B row-major KxN [trans]
// EPI: 0 normal; 1 exp+partials; 2 scale by nsc[n].
// ---------------------------------------------------------------------------
#define STGB 16384   // bytes per operand per stage

template <int TA, int TB, int OUTBF, int EPI>
__global__ __launch_bounds__(128, 2) void bfgemm(
    int M, int N, int K,
    const bf16* __restrict__ A, long long sA,
    const bf16* __restrict__ B, long long sB,
    void* __restrict__ Cv, long long sC,
    const float* __restrict__ bias,
    const float* __restrict__ resid, long long sR,
    float* __restrict__ psum,
    const float* __restrict__ nsc,
    float alpha)
{
    extern __shared__ bf16 smbuf[];     // 3 stages x (A 16KB + B 16KB)
    const int tid = threadIdx.x, lane = tid & 31, wid = tid >> 5;
    const int bm0 = blockIdx.y * 128, bn0 = blockIdx.x * 128;
    const int bz = blockIdx.z;
    A += (size_t)bz * sA;
    B += (size_t)bz * sB;

    const int lda = TA ? M : K;
    const int ldb = TB ? K : N;
    const long long stepA = TA ? (long long)64 * lda : 64;   // per k-tile
    const long long stepB = TB ? 64 : (long long)64 * ldb;

    const uint32_t As_u = cvta_s(smbuf);
    const uint32_t Bs_u = As_u + 3 * STGB;

    // cp.async geometry: loop-invariant swizzle; per-i strides.
    uint32_t aOfs0, aDst0, aOfsStep, bOfs0, bDst0, bOfsStep;
    if (TA == 0) {              // [r][64k]: r=tid>>3, c=tid&7, i-> r+=16
        int r = tid >> 3, c = tid & 7;
        aOfs0 = (uint32_t)(r * lda + c * 8);
        aDst0 = (uint32_t)(r * 8 + (c ^ (r & 7))) * 16;
        aOfsStep = (uint32_t)(16 * lda);
    } else {                    // [k][128m]: k=tid>>4, c=tid&15, i-> k+=8
        int k = tid >> 4, c = tid & 15;
        aOfs0 = (uint32_t)(k * lda + c * 8);
        aDst0 = (uint32_t)(k * 16 + (c ^ (k & 7))) * 16;
        aOfsStep = (uint32_t)(8 * lda);
    }
    if (TB == 1) {
        int r = tid >> 3, c = tid & 7;
        bOfs0 = (uint32_t)(r * ldb + c * 8);
        bDst0 = (uint32_t)(r * 8 + (c ^ (r & 7))) * 16;
        bOfsStep = (uint32_t)(16 * ldb);
    } else {
        int k = tid >> 4, c = tid & 15;
        bOfs0 = (uint32_t)(k * ldb + c * 8);
        bDst0 = (uint32_t)(k * 16 + (c ^ (k & 7))) * 16;
        bOfsStep = (uint32_t)(8 * ldb);
    }
    const bf16* Abase = A + (TA == 0 ? (size_t)bm0 * lda : (size_t)bm0);
    const bf16* Bbase = B + (TB == 1 ? (size_t)bn0 * ldb : (size_t)bn0);

    // ldmatrix fragment byte offsets per ks (0..3)
    const int quad = lane >> 3, lrow = lane & 7;
    const int wm0 = (wid & 1) * 64, wn0 = (wid >> 1) * 64;
    uint32_t fA[4][4], fB[4][4];
    #pragma unroll
    for (int ks = 0; ks < 4; ks++) {
        #pragma unroll
        for (int mi = 0; mi < 4; mi++) {
            if (TA == 0) {
                int r = wm0 + mi * 16 + (quad & 1) * 8 + lrow;
                int c = 2 * ks + (quad >> 1);
                fA[ks][mi] = (uint32_t)(r * 8 + (c ^ (r & 7))) * 16;
            } else {
                int k = ks * 16 + (quad >> 1) * 8 + lrow;
                int c = ((wm0 + mi * 16) >> 3) + (quad & 1);
                fA[ks][mi] = (uint32_t)(k * 16 + (c ^ (k & 7))) * 16;
            }
        }
        #pragma unroll
        for (int nj = 0; nj < 4; nj++) {
            if (TB == 1) {
                int r = wn0 + nj * 16 + (quad & 1) * 8 + lrow;
                int c = 2 * ks + (quad >> 1);
                fB[ks][nj] = (uint32_t)(r * 8 + (c ^ (r & 7))) * 16;
            } else {
                int k = ks * 16 + (quad >> 1) * 8 + lrow;
                int c = ((wn0 + nj * 16) >> 3) + (quad & 1);
                fB[ks][nj] = (uint32_t)(k * 16 + (c ^ (k & 7))) * 16;
            }
        }
    }

    auto issue = [&](int st, const bf16* ag, const bf16* bg) {
        const uint32_t ad = As_u + st * STGB + aDst0;
        const uint32_t bd = Bs_u + st * STGB + bDst0;
        #pragma unroll
        for (int i = 0; i < 8; i++) {
            cpasync16(ad + i * 2048, ag + aOfs0 + (size_t)i * aOfsStep);
            cpasync16(bd + i * 2048, bg + bOfs0 + (size_t)i * bOfsStep);
        }
    };

    uint32_t aFr[2][4][4], bFr[2][4][4];
    auto loadfrag = [&](int set, int st, int ks) {
        const uint32_t ab = As_u + st * STGB;
        const uint32_t bb = Bs_u + st * STGB;
        #pragma unroll
        for (int mi = 0; mi < 4; mi++) {
            if (TA == 0) ldsm4(aFr[set][mi], ab + fA[ks][mi]);
            else         ldsm4t(aFr[set][mi], ab + fA[ks][mi]);
        }
        #pragma unroll
        for (int nj = 0; nj < 4; nj++) {
            if (TB == 1) ldsm4(bFr[set][nj], bb + fB[ks][nj]);
            else         ldsm4t(bFr[set][nj], bb + fB[ks][nj]);
        }
    };

    float acc[4][8][4] = {};
    auto domma = [&](int set) {
        #pragma unroll
        for (int mi = 0; mi < 4; mi++)
            #pragma unroll
            for (int nj = 0; nj < 4; nj++) {
                uint32_t bl[2] = {bFr[set][nj][0], bFr[set][nj][2]};
                uint32_t bh[2] = {bFr[set][nj][1], bFr[set][nj][3]};
                mma_bf16(acc[mi][nj * 2 + 0], aFr[set][mi], bl);
                mma_bf16(acc[mi][nj * 2 + 1], aFr[set][mi], bh);
            }
    };

    const int nk = K / 64;   // >= 8 for all shapes used here
    issue(0, Abase, Bbase);
    asm volatile("cp.async.commit_group;" ::: "memory");
    issue(1, Abase + stepA, Bbase + stepB);
    asm volatile("cp.async.commit_group;" ::: "memory");
    asm volatile("cp.async.wait_group 1;" ::: "memory");
    __syncthreads();
    loadfrag(0, 0, 0);

    // incremental issue pointers (kt+2 tile)
    const bf16* aIss = Abase + 2 * stepA;
    const bf16* bIss = Bbase + 2 * stepB;

    for (int kt = 0; kt < nk; kt++) {
        const int st = kt % 3;
        // stage (kt+2)%3 was last frag-read at iter kt-1, separated from this
        // overwrite by iter kt-1's __syncthreads.
        loadfrag(1, st, 1);
        if (kt + 2 < nk) issue((kt + 2) % 3, aIss, bIss);
        asm volatile("cp.async.commit_group;" ::: "memory");   // uniform count
        aIss += stepA; bIss += stepB;
        domma(0);                                              // ks0
        loadfrag(0, st, 2);
        domma(1);                                              // ks1
        loadfrag(1, st, 3);
        domma(0);                                              // ks2
        asm volatile("cp.async.wait_group 1;" ::: "memory");   // tile kt+1 ready
        __syncthreads();
        if (kt + 1 < nk) loadfrag(0, (kt + 1) % 3, 0);
        domma(1);                                              // ks3
    }

    // ---------------- epilogue ----------------
    const int lr = lane >> 2, lc = lane & 3;

    if (EPI == 1) {
        __syncthreads();
        float* ps = (float*)smbuf;             // [128][2]
        bf16* C = (bf16*)Cv + (size_t)bz * sC;
        #pragma unroll
        for (int mi = 0; mi < 4; mi++) {
            const int r0 = bm0 + wm0 + mi * 16 + lr;
            const int col = bn0 + wn0 + 2 * lc;
            uint32_t* C0 = (uint32_t*)(C + (size_t)r0 * N + col);
            uint32_t* C1 = (uint32_t*)(C + (size_t)(r0 + 8) * N + col);
            float s0 = 0.f, s1 = 0.f;
            #pragma unroll
            for (int j = 0; j < 8; j++) {
                float e00 = __expf(acc[mi][j][0] * alpha);
                float e01 = __expf(acc[mi][j][1] * alpha);
                float e10 = __expf(acc[mi][j][2] * alpha);
                float e11 = __expf(acc[mi][j][3] * alpha);
                C0[j * 4] = packbf(e00, e01);
                C1[j * 4] = packbf(e10, e11);
                s0 += e00 + e01;
                s1 += e10 + e11;
            }
            float v0 = s0, v1 = s1;
            v0 += __shfl_xor_sync(0xffffffffu, v0, 1);
            v0 += __shfl_xor_sync(0xffffffffu, v0, 2);
            v1 += __shfl_xor_sync(0xffffffffu, v1, 1);
            v1 += __shfl_xor_sync(0xffffffffu, v1, 2);
            if (lc == 0) {
                ps[(wm0 + mi * 16 + lr) * 2 + (wn0 >> 6)] = v0;
                ps[(wm0 + mi * 16 + 8 + lr) * 2 + (wn0 >> 6)] = v1;
            }
        }
        __syncthreads();
        float t = ps[tid * 2 + 0] + ps[tid * 2 + 1];
        psum[((size_t)bz * HW + bm0 + tid) * 32 + blockIdx.x] = t;
        return;
    }

    #pragma unroll
    for (int mi = 0; mi < 4; mi++) {
        const int r0 = bm0 + wm0 + mi * 16 + lr;
        const int col = bn0 + wn0 + 2 * lc;
        if (OUTBF) {
            bf16* C = (bf16*)Cv + (size_t)bz * sC;
            uint32_t* C0 = (uint32_t*)(C + (size_t)r0 * N + col);
            uint32_t* C1 = (uint32_t*)(C + (size_t)(r0 + 8) * N + col);
            const float bv0 = (EPI == 0 && bias) ? bias[r0] : 0.f;
            const float bv1 = (EPI == 0 && bias) ? bias[r0 + 8] : 0.f;
            #pragma unroll
            for (int j = 0; j < 8; j++) {
                float f0 = 1.f, f1 = 1.f;
                if (EPI == 2) {
                    float2 ff = *(const float2*)(nsc + (size_t)bz * HW + col + j * 8);
                    f0 = ff.x; f1 = ff.y;
                }
                C0[j * 4] = packbf(acc[mi][j][0] * alpha * f0 + bv0,
                                   acc[mi][j][1] * alpha * f1 + bv0);
                C1[j * 4] = packbf(acc[mi][j][2] * alpha * f0 + bv1,
                                   acc[mi][j][3] * alpha * f1 + bv1);
            }
        } else {
            float* C = (float*)Cv + (size_t)bz * sC;
            float* C0 = C + (size_t)r0 * N + col;
            float* C1 = C + (size_t)(r0 + 8) * N + col;
            const float bv0 = bias ? bias[r0] : 0.f;
            const float bv1 = bias ? bias[r0 + 8] : 0.f;
            const float* R0 = resid ? resid + (size_t)bz * sR + (size_t)r0 * N + col : (const float*)0;
            const float* R1 = resid ? resid + (size_t)bz * sR + (size_t)(r0 + 8) * N + col : (const float*)0;
            #pragma unroll
            for (int j = 0; j < 8; j++) {
                float2 v0 = make_float2(acc[mi][j][0] * alpha + bv0,
                                        acc[mi][j][1] * alpha + bv0);
                float2 v1 = make_float2(acc[mi][j][2] * alpha + bv1,
                                        acc[mi][j][3] * alpha + bv1);
                if (resid) {
                    float2 q0 = *(const float2*)(R0 + j * 8);
                    float2 q1 = *(const float2*)(R1 + j * 8);
                    v0.x += q0.x; v0.y += q0.y;
                    v1.x += q1.x; v1.y += q1.y;
                }
                *(float2*)(C0 + j * 8) = v0;
                *(float2*)(C1 + j * 8) = v1;
            }
        }
    }
}

// ---------------------------------------------------------------------------
// rowinv: 1 / sum of 32 partials per row
// ---------------------------------------------------------------------------
__global__ __launch_bounds__(256) void rowinv_kernel(
    const float* __restrict__ psum, float* __restrict__ rinv)
{
    const int idx = blockIdx.x * 256 + threadIdx.x;
    const float4* p = (const float4*)(psum + (size_t)idx * 32);
    float s = 0.f;
    #pragma unroll
    for (int i = 0; i < 8; i++) {
        float4 v = p[i];
        s += v.x + v.y + v.z + v.w;
    }
    rinv[idx] = 1.f / s;
}

// ---------------------------------------------------------------------------
// Launcher
// ---------------------------------------------------------------------------
extern "C" void kernel_launch(void* const* d_in, const int* in_sizes, int n_in,
                              void* d_out, int out_size)
{
    (void)in_sizes; (void)n_in; (void)out_size;
    const float* x    = (const float*)d_in[0];
    const float* gn_w = (const float*)d_in[1];
    const float* gn_b = (const float*)d_in[2];
    const float* wq   = (const float*)d_in[3];
    const float* bq   = (const float*)d_in[4];
    const float* wk   = (const float*)d_in[5];
    const float* bk   = (const float*)d_in[6];
    const float* wv   = (const float*)d_in[7];
    const float* bv   = (const float*)d_in[8];
    const float* wo   = (const float*)d_in[9];
    const float* bo   = (const float*)d_in[10];
    float* out = (float*)d_out;

    bf16 *h_, *qkv, *o, *p, *w;
    float *bqkv, *ps, *ri;
    cudaGetSymbolAddress((void**)&h_,  g_h);
    cudaGetSymbolAddress((void**)&qkv, g_qkv);
    cudaGetSymbolAddress((void**)&o,   g_o);
    cudaGetSymbolAddress((void**)&p,   g_p);
    cudaGetSymbolAddress((void**)&w,   g_w);
    cudaGetSymbolAddress((void**)&bqkv, g_bqkv);
    cudaGetSymbolAddress((void**)&ps,  g_ps);
    cudaGetSymbolAddress((void**)&ri,  g_ri);

    const int SMEM = 98304;  // 3 stages x (16KB A + 16KB B)
    cudaFuncSetAttribute(bfgemm<0, 0, 1, 0>, cudaFuncAttributeMaxDynamicSharedMemorySize, SMEM);
    cudaFuncSetAttribute(bfgemm<1, 0, 1, 1>, cudaFuncAttributeMaxDynamicSharedMemorySize, SMEM);
    cudaFuncSetAttribute(bfgemm<0, 1, 1, 2>, cudaFuncAttributeMaxDynamicSharedMemorySize, SMEM);
    cudaFuncSetAttribute(bfgemm<0, 0, 0, 0>, cudaFuncAttributeMaxDynamicSharedMemorySize, SMEM);

    const long long SC  = (long long)C512 * HW;
    const long long SC3 = 3 * SC;
    const long long SS  = (long long)HW * HW;
    const int WSZ = C512 * C512;
    const float scale = 0.044194173824159216f;    // 512^-0.5

    convw_kernel<<<4096, 256>>>(wq, wk, wv, wo, w);
    convb_kernel<<<6, 256>>>(bq, bk, bv, bqkv);
    groupnorm_kernel<<<B4 * NG, 256>>>(x, gn_w, gn_b, h_);

    // Fused QKV: qkv[m][s] = sum_c Wqkv[m][c] * h[c][s] + bqkv[m]
    dim3 gQKV(HW / 128, 1536 / 128, B4);
    bfgemm<0, 0, 1, 0><<<gQKV, 128, SMEM>>>(1536, HW, C512,
        w, 0, h_, SC, qkv, SC3, bqkv, nullptr, 0, nullptr, nullptr, 1.f);

    // p[i][j] = exp(scale * sum_c q[c][i] k[c][j]); partial row sums
    dim3 gS(HW / 128, HW / 128, B4);
    bfgemm<1, 0, 1, 1><<<gS, 128, SMEM>>>(HW, HW, C512,
        qkv, SC3, qkv + SC, SC3, p, SS, nullptr, nullptr, 0, ps, nullptr, scale);

    rowinv_kernel<<<B4 * HW / 256, 256>>>(ps, ri);

    // o[c][i] = (sum_j v[c][j] * p[i][j]) * rinv[i]
    dim3 gO(HW / 128, C512 / 128, B4);
    bfgemm<0, 1, 1, 2><<<gO, 128, SMEM>>>(C512, HW, HW,
        qkv + 2 * SC, SC3, p, SS, o, SC, nullptr, nullptr, 0, nullptr, ri, 1.f);

    // out[m][s] = sum_c Wo[m][c] * o[c][s] + bo[m] + x[m][s]
    bfgemm<0, 0, 0, 0><<<gO, 128, SMEM>>>(C512, HW, C512,
        w + 3 * WSZ, 0, o, SC, out, SC, bo, x, SC, nullptr, nullptr, 1.f);
}